// round 9
// baseline (speedup 1.0000x reference)
#include <cuda_runtime.h>
#include <cuda_fp16.h>
#include <cstdint>
#include <cstddef>

// Harness PTX target is base sm_103 — no tcgen05. Tensor path: mma.sync f16 m16n8k16.
// Round 9: L1-bound fix. 64x64 warp tiles (max fragment reuse), 4-warp CTAs,
// 2 CTAs/SM for barrier-phase interleave. Fragment loads double-buffered across ks.

// ---------------- problem constants ----------------
#define N_TOK   16384
#define F_DIM   1024
#define B_DIM   512
#define TILE_M  128
#define TILE_F  32
#define GCOLS   128          // 4 gates * TILE_F
#define KC      64           // K elements per chunk (128B fp16 rows)
#define NCHUNK  24           // 1536 / 64
#define THREADS 128
#define STAGES  3

// ---------------- smem layout ----------------
#define ABYTES      (TILE_M * KC * 2)          // 16384
#define BBYTES      (GCOLS * KC * 2)           // 16384
#define STAGE_BYTES (ABYTES + BBYTES)          // 32768
#define GSM_PITCH   36
#define GSM_BYTES   (4 * 128 * GSM_PITCH * 4)  // 73728 (epilogue, unions stages)
#define SM_BIAS     (STAGES * STAGE_BYTES)     // 98304
#define SMEM_TOTAL  (SM_BIAS + 128 * 4)        // 98816  (x2 CTAs = 197632)

static_assert(GSM_BYTES <= STAGES * STAGE_BYTES, "epilogue union");
static_assert(2 * SMEM_TOTAL <= 227 * 1024, "2 CTAs/SM smem");

// ---------------- fp16 scratch ----------------
#define NH  (N_TOK * F_DIM)
#define NX  (N_TOK * B_DIM)
#define NWH (4 * F_DIM * F_DIM)
#define NWX (4 * F_DIM * B_DIM)
__device__ __half g_h [NH];
__device__ __half g_x [NX];
__device__ __half g_wh[NWH];
__device__ __half g_wx[NWX];

// ---------------- helpers ----------------
static __device__ __forceinline__ uint32_t smem_u32(const void* p) {
    uint32_t a;
    asm("{ .reg .u64 t; cvta.to.shared.u64 t, %1; cvt.u32.u64 %0, t; }" : "=r"(a) : "l"(p));
    return a;
}

static __device__ __forceinline__ void cp16(uint32_t dst, const void* src) {
    asm volatile("cp.async.cg.shared.global [%0], [%1], 16;" :: "r"(dst), "l"(src) : "memory");
}

static __device__ __forceinline__ void ldsm4(uint32_t* r, uint32_t addr) {
    asm volatile("ldmatrix.sync.aligned.m8n8.x4.shared.b16 {%0,%1,%2,%3}, [%4];"
                 : "=r"(r[0]), "=r"(r[1]), "=r"(r[2]), "=r"(r[3]) : "r"(addr));
}

static __device__ __forceinline__ void mma_f16(float* c, const uint32_t* a, const uint32_t* b) {
    asm volatile(
        "mma.sync.aligned.m16n8k16.row.col.f32.f16.f16.f32 "
        "{%0,%1,%2,%3}, {%4,%5,%6,%7}, {%8,%9}, {%0,%1,%2,%3};"
        : "+f"(c[0]), "+f"(c[1]), "+f"(c[2]), "+f"(c[3])
        : "r"(a[0]), "r"(a[1]), "r"(a[2]), "r"(a[3]), "r"(b[0]), "r"(b[1]));
}

static __device__ __forceinline__ float sigf(float x) { return 1.0f / (1.0f + __expf(-x)); }
static __device__ __forceinline__ float tanh_fast(float x) {
    return 2.0f / (1.0f + __expf(-2.0f * x)) - 1.0f;
}

// ---------------- merged pre-pass: all four tensors in ONE launch ----------------
__global__ void __launch_bounds__(256) preconv_all(const float4* __restrict__ s_h,
                                                   const float4* __restrict__ s_x,
                                                   const float4* __restrict__ s_wh,
                                                   const float4* __restrict__ s_wx) {
    const int T1 = NH / 8, T2 = T1 + NX / 8, T3 = T2 + NWH / 8, T4 = T3 + NWX / 8;
    int i = blockIdx.x * 256 + threadIdx.x;
    if (i >= T4) return;
    const float4* src;
    uint4* dst;
    int j = i;
    if (i < T1)      { src = s_h;  dst = (uint4*)g_h; }
    else if (i < T2) { src = s_x;  dst = (uint4*)g_x;  j = i - T1; }
    else if (i < T3) { src = s_wh; dst = (uint4*)g_wh; j = i - T2; }
    else             { src = s_wx; dst = (uint4*)g_wx; j = i - T3; }
    float4 a = src[2 * j], b = src[2 * j + 1];
    __half2 p0 = __floats2half2_rn(a.x, a.y);
    __half2 p1 = __floats2half2_rn(a.z, a.w);
    __half2 p2 = __floats2half2_rn(b.x, b.y);
    __half2 p3 = __floats2half2_rn(b.z, b.w);
    uint4 o;
    o.x = *reinterpret_cast<uint32_t*>(&p0);
    o.y = *reinterpret_cast<uint32_t*>(&p1);
    o.z = *reinterpret_cast<uint32_t*>(&p2);
    o.w = *reinterpret_cast<uint32_t*>(&p3);
    dst[j] = o;
}

// ---------------- mainloop chunk loader ----------------
static __device__ __forceinline__ void issue_chunk(int chunk, int slot, uint32_t sb, int tid,
                                                   int m_base, int c_base) {
    const __half *asrc, *wk;
    int ld;
    if (chunk < 16) {                 // K in [0,1024): h_prev @ Wh^T
        asrc = g_h + (size_t)m_base * F_DIM + chunk * KC;
        wk   = g_wh + chunk * KC;
        ld   = F_DIM;
    } else {                          // K in [1024,1536): behavior @ Wx^T
        asrc = g_x + (size_t)m_base * B_DIM + (chunk - 16) * KC;
        wk   = g_wx + (chunk - 16) * KC;
        ld   = B_DIM;
    }

    const uint32_t abase = sb + (uint32_t)slot * STAGE_BYTES;
#pragma unroll
    for (int i = 0; i < 8; ++i) {     // A: 128 rows x 8 units = 1024 float4 units
        int idx = tid + i * THREADS;
        int row = idx >> 3, u = idx & 7;
        cp16(abase + row * 128 + (uint32_t)((u ^ (row & 7)) << 4),
             asrc + (size_t)row * ld + u * 8);
    }
    const uint32_t bbase = abase + ABYTES;
#pragma unroll
    for (int i = 0; i < 8; ++i) {     // B: 128 rows x 8 units
        int idx = tid + i * THREADS;
        int rr = idx >> 3, u = idx & 7;
        int g = rr >> 5, r = rr & 31;
        cp16(bbase + rr * 128 + (uint32_t)((u ^ (rr & 7)) << 4),
             wk + (size_t)(g * F_DIM + c_base + r) * ld + u * 8);
    }
    asm volatile("cp.async.commit_group;" ::: "memory");
}

__global__ void __launch_bounds__(THREADS, 2)
lstm_mma_kernel(float* __restrict__ out,
                const float* __restrict__ c_prev,
                const float* __restrict__ bias) {
    extern __shared__ char smem[];
    const uint32_t sb = smem_u32(smem);
    const int tid = threadIdx.x;
    const int lane = tid & 31;
    const int wid = tid >> 5;          // 4 warps
    const int warp_m = wid & 1;        // token half (64 rows)
    const int warp_n = wid >> 1;       // gemm-col half (64 cols = 2 gates)
    const int la = lane >> 2;          // 0..7
    const int lk = lane & 3;           // 0..3

    const int f_tile = blockIdx.x & 31;
    const int m_tile = blockIdx.x >> 5;
    const int m_base = m_tile * TILE_M;
    const int c_base = f_tile * TILE_F;

    float* bias_s = reinterpret_cast<float*>(smem + SM_BIAS);
    bias_s[tid] = bias[(tid >> 5) * F_DIM + c_base + (tid & 31)];

    // ---- per-lane ldmatrix address components ----
    const int q    = lane >> 3;        // quad / matrix index
    const int lrow = lane & 7;
    const uint32_t aStat = (uint32_t)(warp_m * 64 + (q & 1) * 8 + lrow) * 128u;
    const int kqA = q >> 1;
    const uint32_t bStat = (uint32_t)(warp_n * 64 + (q >> 1) * 8 + lrow) * 128u;
    const int kqB = q & 1;

    float acc[4][8][4];
#pragma unroll
    for (int mt = 0; mt < 4; ++mt)
#pragma unroll
        for (int nt = 0; nt < 8; ++nt)
#pragma unroll
            for (int j = 0; j < 4; ++j) acc[mt][nt][j] = 0.0f;

    issue_chunk(0, 0, sb, tid, m_base, c_base);
    issue_chunk(1, 1, sb, tid, m_base, c_base);

    int slot = 0, wslot = 2;
    for (int ch = 0; ch < NCHUNK; ++ch) {
        if (ch < NCHUNK - 1) {
            asm volatile("cp.async.wait_group 1;" ::: "memory");
        } else {
            asm volatile("cp.async.wait_group 0;" ::: "memory");
        }
        __syncthreads();

        if (ch + 2 < NCHUNK) {
            issue_chunk(ch + 2, wslot, sb, tid, m_base, c_base);
            if (++wslot == STAGES) wslot = 0;
        }

        const uint32_t abase = sb + (uint32_t)slot * STAGE_BYTES;
        const uint32_t bbase = abase + ABYTES;
        if (++slot == STAGES) slot = 0;

        // fragment double buffers across ks (load ks+1 while computing ks)
        uint32_t af[2][4][4], bq[2][4][4];

#define LOAD_FRAGS(KS, BUF)                                                      \
        do {                                                                     \
            const uint32_t uA = (uint32_t)(((2 * (KS) + kqA) ^ lrow) << 4);      \
            const uint32_t uB = (uint32_t)(((2 * (KS) + kqB) ^ lrow) << 4);      \
            _Pragma("unroll")                                                    \
            for (int mt = 0; mt < 4; ++mt)                                       \
                ldsm4(af[BUF][mt], abase + aStat + (uint32_t)(mt * 2048) + uA);  \
            _Pragma("unroll")                                                    \
            for (int np = 0; np < 4; ++np)                                       \
                ldsm4(bq[BUF][np], bbase + bStat + (uint32_t)(np * 2048) + uB);  \
        } while (0)

        LOAD_FRAGS(0, 0);
#pragma unroll
        for (int ks = 0; ks < 4; ++ks) {
            const int cur = ks & 1;
            if (ks < 3) LOAD_FRAGS(ks + 1, cur ^ 1);
#pragma unroll
            for (int mt = 0; mt < 4; ++mt)
#pragma unroll
                for (int nt = 0; nt < 8; ++nt)
                    mma_f16(acc[mt][nt], af[cur][mt], &bq[cur][nt >> 1][(nt & 1) * 2]);
        }
#undef LOAD_FRAGS
    }
    __syncthreads();   // stage buffers -> epilogue union

    // ---- epilogue: dump gate tiles to smem ----
    // gemm-col = warp_n*64 + nt*8 + 2lk(+1); gate = col>>5; f = col&31
    float* gsm = reinterpret_cast<float*>(smem);
#pragma unroll
    for (int mt = 0; mt < 4; ++mt) {
#pragma unroll
        for (int nt = 0; nt < 8; ++nt) {
            const int r0 = warp_m * 64 + mt * 16 + la;
            const int col0 = warp_n * 64 + nt * 8 + 2 * lk;
            const int gate = col0 >> 5;
            const int f0 = col0 & 31;
            const size_t o = ((size_t)(gate * 128 + r0)) * GSM_PITCH + f0;
            gsm[o]     = acc[mt][nt][0];
            gsm[o + 1] = acc[mt][nt][1];
            gsm[o + 8 * GSM_PITCH]     = acc[mt][nt][2];
            gsm[o + 8 * GSM_PITCH + 1] = acc[mt][nt][3];
        }
    }
    __syncthreads();

    // ---- gate math + coalesced global I/O ----
    const float* cpg = c_prev + (size_t)m_base * F_DIM + c_base;
    float* og = out + (size_t)m_base * F_DIM + c_base;
#pragma unroll
    for (int i = 0; i < (TILE_M * TILE_F) / THREADS; ++i) {
        const int idx = tid + i * THREADS;
        const int row = idx >> 5;
        const int f = idx & 31;
        const float xi = gsm[((size_t)(0 * 128 + row)) * GSM_PITCH + f] + bias_s[f];
        const float xf = gsm[((size_t)(1 * 128 + row)) * GSM_PITCH + f] + bias_s[32 + f];
        const float xg = gsm[((size_t)(2 * 128 + row)) * GSM_PITCH + f] + bias_s[64 + f];
        const float xo = gsm[((size_t)(3 * 128 + row)) * GSM_PITCH + f] + bias_s[96 + f];
        const float cv = sigf(xf) * cpg[(size_t)row * F_DIM + f] + sigf(xi) * tanh_fast(xg);
        og[(size_t)row * F_DIM + f] = sigf(xo) * tanh_fast(cv);
    }
}

extern "C" void kernel_launch(void* const* d_in, const int* in_sizes, int n_in,
                              void* d_out, int out_size) {
    const float* behavior = (const float*)d_in[0];
    const float* h_prev   = (const float*)d_in[1];
    const float* c_prev   = (const float*)d_in[2];
    const float* Wh       = (const float*)d_in[3];
    const float* Wx       = (const float*)d_in[4];
    const float* bias     = (const float*)d_in[5];

    const int total8 = NH / 8 + NX / 8 + NWH / 8 + NWX / 8;
    preconv_all<<<(total8 + 255) / 256, 256>>>(
        (const float4*)h_prev, (const float4*)behavior,
        (const float4*)Wh, (const float4*)Wx);

    cudaFuncSetAttribute(lstm_mma_kernel,
                         cudaFuncAttributeMaxDynamicSharedMemorySize, SMEM_TOTAL);

    const int grid = (N_TOK / TILE_M) * (F_DIM / TILE_F);  // 128 * 32 = 4096
    lstm_mma_kernel<<<grid, THREADS, SMEM_TOTAL>>>((float*)d_out, c_prev, bias);
}

// round 10
// speedup vs baseline: 1.3106x; 1.3106x over previous
#include <cuda_runtime.h>
#include <cuda_fp16.h>
#include <cstdint>
#include <cstddef>

// Harness PTX target is base sm_103 — no tcgen05. Tensor path: mma.sync f16 m16n8k16
// (fallback HMMA, measured rt~8 cyc/SMSP, busy floor ~340us). R7 shape (16 warps/SM,
// warp tile 64x32, 2 CTAs/SM) + merged prepass + issue-after-compute + cprev prefetch.

// ---------------- problem constants ----------------
#define N_TOK   16384
#define F_DIM   1024
#define B_DIM   512
#define TILE_M  128
#define TILE_F  32
#define GCOLS   128          // 4 gates * TILE_F
#define KC      64           // K elements per chunk (128B fp16 rows)
#define NCHUNK  24           // 1536 / 64
#define THREADS 256
#define STAGES  3

// ---------------- smem layout ----------------
#define ABYTES      (TILE_M * KC * 2)          // 16384
#define BBYTES      (GCOLS * KC * 2)           // 16384
#define STAGE_BYTES (ABYTES + BBYTES)          // 32768
#define GSM_PITCH   36
#define GSM_BYTES   (4 * 128 * GSM_PITCH * 4)  // 73728 (epilogue, unions stages)
#define SM_BIAS     (STAGES * STAGE_BYTES)     // 98304
#define SMEM_TOTAL  (SM_BIAS + 128 * 4)        // 98816  (x2 CTAs = 197632)

static_assert(GSM_BYTES <= STAGES * STAGE_BYTES, "epilogue union");
static_assert(2 * SMEM_TOTAL <= 227 * 1024, "2 CTAs/SM smem");

// ---------------- fp16 scratch ----------------
#define NH  (N_TOK * F_DIM)
#define NX  (N_TOK * B_DIM)
#define NWH (4 * F_DIM * F_DIM)
#define NWX (4 * F_DIM * B_DIM)
__device__ __half g_h [NH];
__device__ __half g_x [NX];
__device__ __half g_wh[NWH];
__device__ __half g_wx[NWX];

// ---------------- helpers ----------------
static __device__ __forceinline__ uint32_t smem_u32(const void* p) {
    uint32_t a;
    asm("{ .reg .u64 t; cvta.to.shared.u64 t, %1; cvt.u32.u64 %0, t; }" : "=r"(a) : "l"(p));
    return a;
}

static __device__ __forceinline__ void cp16(uint32_t dst, const void* src) {
    asm volatile("cp.async.cg.shared.global [%0], [%1], 16;" :: "r"(dst), "l"(src) : "memory");
}

static __device__ __forceinline__ void ldsm4(uint32_t* r, uint32_t addr) {
    asm volatile("ldmatrix.sync.aligned.m8n8.x4.shared.b16 {%0,%1,%2,%3}, [%4];"
                 : "=r"(r[0]), "=r"(r[1]), "=r"(r[2]), "=r"(r[3]) : "r"(addr));
}

static __device__ __forceinline__ void mma_f16(float* c, const uint32_t* a, const uint32_t* b) {
    asm volatile(
        "mma.sync.aligned.m16n8k16.row.col.f32.f16.f16.f32 "
        "{%0,%1,%2,%3}, {%4,%5,%6,%7}, {%8,%9}, {%0,%1,%2,%3};"
        : "+f"(c[0]), "+f"(c[1]), "+f"(c[2]), "+f"(c[3])
        : "r"(a[0]), "r"(a[1]), "r"(a[2]), "r"(a[3]), "r"(b[0]), "r"(b[1]));
}

static __device__ __forceinline__ float sigf(float x) { return 1.0f / (1.0f + __expf(-x)); }
static __device__ __forceinline__ float tanh_fast(float x) {
    return 2.0f / (1.0f + __expf(-2.0f * x)) - 1.0f;
}

// ---------------- merged pre-pass: all four tensors in ONE launch ----------------
__global__ void __launch_bounds__(256) preconv_all(const float4* __restrict__ s_h,
                                                   const float4* __restrict__ s_x,
                                                   const float4* __restrict__ s_wh,
                                                   const float4* __restrict__ s_wx) {
    const int T1 = NH / 8, T2 = T1 + NX / 8, T3 = T2 + NWH / 8, T4 = T3 + NWX / 8;
    int i = blockIdx.x * 256 + threadIdx.x;
    if (i >= T4) return;
    const float4* src;
    uint4* dst;
    int j = i;
    if (i < T1)      { src = s_h;  dst = (uint4*)g_h; }
    else if (i < T2) { src = s_x;  dst = (uint4*)g_x;  j = i - T1; }
    else if (i < T3) { src = s_wh; dst = (uint4*)g_wh; j = i - T2; }
    else             { src = s_wx; dst = (uint4*)g_wx; j = i - T3; }
    float4 a = src[2 * j], b = src[2 * j + 1];
    __half2 p0 = __floats2half2_rn(a.x, a.y);
    __half2 p1 = __floats2half2_rn(a.z, a.w);
    __half2 p2 = __floats2half2_rn(b.x, b.y);
    __half2 p3 = __floats2half2_rn(b.z, b.w);
    uint4 o;
    o.x = *reinterpret_cast<uint32_t*>(&p0);
    o.y = *reinterpret_cast<uint32_t*>(&p1);
    o.z = *reinterpret_cast<uint32_t*>(&p2);
    o.w = *reinterpret_cast<uint32_t*>(&p3);
    dst[j] = o;
}

// ---------------- mainloop chunk loader ----------------
static __device__ __forceinline__ void issue_chunk(int chunk, int slot, uint32_t sb, int tid,
                                                   int m_base, int c_base) {
    const __half *asrc, *wk;
    int ld;
    if (chunk < 16) {                 // K in [0,1024): h_prev @ Wh^T
        asrc = g_h + (size_t)m_base * F_DIM + chunk * KC;
        wk   = g_wh + chunk * KC;
        ld   = F_DIM;
    } else {                          // K in [1024,1536): behavior @ Wx^T
        asrc = g_x + (size_t)m_base * B_DIM + (chunk - 16) * KC;
        wk   = g_wx + (chunk - 16) * KC;
        ld   = B_DIM;
    }

    const uint32_t abase = sb + (uint32_t)slot * STAGE_BYTES;
#pragma unroll
    for (int i = 0; i < 4; ++i) {     // A: 128 rows x 128B, SW128
        int idx = tid + i * THREADS;
        int row = idx >> 3, u = idx & 7;
        cp16(abase + row * 128 + (uint32_t)((u ^ (row & 7)) << 4),
             asrc + (size_t)row * ld + u * 8);
    }
    const uint32_t bbase = abase + ABYTES;
#pragma unroll
    for (int i = 0; i < 4; ++i) {     // B: 128 rows x 128B, SW128
        int idx = tid + i * THREADS;
        int rr = idx >> 3, u = idx & 7;
        int g = rr >> 5, r = rr & 31;
        cp16(bbase + rr * 128 + (uint32_t)((u ^ (rr & 7)) << 4),
             wk + (size_t)(g * F_DIM + c_base + r) * ld + u * 8);
    }
    asm volatile("cp.async.commit_group;" ::: "memory");
}

__global__ void __launch_bounds__(THREADS, 2)
lstm_mma_kernel(float* __restrict__ out,
                const float* __restrict__ c_prev,
                const float* __restrict__ bias) {
    extern __shared__ char smem[];
    const uint32_t sb = smem_u32(smem);
    const int tid = threadIdx.x;
    const int lane = tid & 31;
    const int wid = tid >> 5;
    const int warp_m = wid & 1;        // token half (64 rows)
    const int warp_n = wid >> 1;       // gate (0..3), 32 gemm-cols each
    const int la = lane >> 2;          // 0..7
    const int lk = lane & 3;           // 0..3

    const int f_tile = blockIdx.x & 31;
    const int m_tile = blockIdx.x >> 5;
    const int m_base = m_tile * TILE_M;
    const int c_base = f_tile * TILE_F;

    float* bias_s = reinterpret_cast<float*>(smem + SM_BIAS);
    if (tid < 128) bias_s[tid] = bias[(tid >> 5) * F_DIM + c_base + (tid & 31)];

    // ---- per-lane ldmatrix address components ----
    const int q    = lane >> 3;        // quad / matrix index
    const int lrow = lane & 7;
    const uint32_t aStat = (uint32_t)(warp_m * 64 + (q & 1) * 8 + lrow) * 128u;
    const int kqA = q >> 1;
    const uint32_t bStat = (uint32_t)(warp_n * 32 + (q >> 1) * 8 + lrow) * 128u;
    const int kqB = q & 1;

    float acc[4][4][4];
#pragma unroll
    for (int mt = 0; mt < 4; ++mt)
#pragma unroll
        for (int nt = 0; nt < 4; ++nt)
#pragma unroll
            for (int j = 0; j < 4; ++j) acc[mt][nt][j] = 0.0f;

    issue_chunk(0, 0, sb, tid, m_base, c_base);
    issue_chunk(1, 1, sb, tid, m_base, c_base);

#pragma unroll 3
    for (int ch = 0; ch < NCHUNK; ++ch) {
        if (ch < NCHUNK - 1) {
            asm volatile("cp.async.wait_group 1;" ::: "memory");
        } else {
            asm volatile("cp.async.wait_group 0;" ::: "memory");
        }
        __syncthreads();

        const uint32_t abase = sb + (uint32_t)(ch % STAGES) * STAGE_BYTES;
        const uint32_t bbase = abase + ABYTES;

        // compute FIRST (tensor pipe starts immediately after the barrier)
#pragma unroll
        for (int ks = 0; ks < 4; ++ks) {          // 4 x K=16 per chunk
            const uint32_t uA = (uint32_t)(((2 * ks + kqA) ^ lrow) << 4);
            const uint32_t uB = (uint32_t)(((2 * ks + kqB) ^ lrow) << 4);

            uint32_t af[4][4];
#pragma unroll
            for (int mt = 0; mt < 4; ++mt)
                ldsm4(af[mt], abase + aStat + (uint32_t)(mt * 2048) + uA);

            uint32_t bq[2][4];                    // each x4 covers 2 n-tiles
#pragma unroll
            for (int np = 0; np < 2; ++np)
                ldsm4(bq[np], bbase + bStat + (uint32_t)(np * 2048) + uB);

#pragma unroll
            for (int mt = 0; mt < 4; ++mt)
#pragma unroll
                for (int nt = 0; nt < 4; ++nt)
                    mma_f16(acc[mt][nt], af[mt], &bq[nt >> 1][(nt & 1) * 2]);
        }

        // issue the next chunk AFTER compute (still ~1.5 chunks of lead time)
        if (ch + 2 < NCHUNK)
            issue_chunk(ch + 2, (ch + 2) % STAGES, sb, tid, m_base, c_base);
    }

    // ---- prefetch c_prev into registers (latency hides under gsm writes) ----
    const float* cpg = c_prev + (size_t)m_base * F_DIM + c_base;
    float cpv[(TILE_M * TILE_F) / THREADS];
#pragma unroll
    for (int i = 0; i < (TILE_M * TILE_F) / THREADS; ++i) {
        const int idx = tid + i * THREADS;
        cpv[i] = cpg[(size_t)(idx >> 5) * F_DIM + (idx & 31)];
    }

    __syncthreads();   // stage buffers -> epilogue union

    // ---- epilogue: dump 4 gate tiles (128 x 32 each) to smem ----
    float* gsm = reinterpret_cast<float*>(smem);
#pragma unroll
    for (int mt = 0; mt < 4; ++mt) {
#pragma unroll
        for (int nt = 0; nt < 4; ++nt) {
            const int r0 = warp_m * 64 + mt * 16 + la;
            const int f0 = nt * 8 + 2 * lk;
            const size_t o = ((size_t)(warp_n * 128 + r0)) * GSM_PITCH + f0;
            gsm[o]     = acc[mt][nt][0];
            gsm[o + 1] = acc[mt][nt][1];
            gsm[o + 8 * GSM_PITCH]     = acc[mt][nt][2];
            gsm[o + 8 * GSM_PITCH + 1] = acc[mt][nt][3];
        }
    }
    __syncthreads();

    // ---- gate math + coalesced global I/O ----
    float* og = out + (size_t)m_base * F_DIM + c_base;
#pragma unroll
    for (int i = 0; i < (TILE_M * TILE_F) / THREADS; ++i) {
        const int idx = tid + i * THREADS;
        const int row = idx >> 5;
        const int f = idx & 31;
        const float xi = gsm[((size_t)(0 * 128 + row)) * GSM_PITCH + f] + bias_s[f];
        const float xf = gsm[((size_t)(1 * 128 + row)) * GSM_PITCH + f] + bias_s[32 + f];
        const float xg = gsm[((size_t)(2 * 128 + row)) * GSM_PITCH + f] + bias_s[64 + f];
        const float xo = gsm[((size_t)(3 * 128 + row)) * GSM_PITCH + f] + bias_s[96 + f];
        const float cv = sigf(xf) * cpv[i] + sigf(xi) * tanh_fast(xg);
        og[(size_t)row * F_DIM + f] = sigf(xo) * tanh_fast(cv);
    }
}

extern "C" void kernel_launch(void* const* d_in, const int* in_sizes, int n_in,
                              void* d_out, int out_size) {
    const float* behavior = (const float*)d_in[0];
    const float* h_prev   = (const float*)d_in[1];
    const float* c_prev   = (const float*)d_in[2];
    const float* Wh       = (const float*)d_in[3];
    const float* Wx       = (const float*)d_in[4];
    const float* bias     = (const float*)d_in[5];

    const int total8 = NH / 8 + NX / 8 + NWH / 8 + NWX / 8;
    preconv_all<<<(total8 + 255) / 256, 256>>>(
        (const float4*)h_prev, (const float4*)behavior,
        (const float4*)Wh, (const float4*)Wx);

    cudaFuncSetAttribute(lstm_mma_kernel,
                         cudaFuncAttributeMaxDynamicSharedMemorySize, SMEM_TOTAL);

    const int grid = (N_TOK / TILE_M) * (F_DIM / TILE_F);  // 128 * 32 = 4096
    lstm_mma_kernel<<<grid, THREADS, SMEM_TOTAL>>>((float*)d_out, c_prev, bias);
}

// round 11
// speedup vs baseline: 1.3336x; 1.0175x over previous
#include <cuda_runtime.h>
#include <cuda_fp16.h>
#include <cstdint>
#include <cstddef>

// Harness PTX target is base sm_103 — no tcgen05. Tensor path: mma.sync f16 m16n8k16
// (fallback HMMA, rt~8 cyc/SMSP -> ~341us busy floor). R10 shape (16 warps/SM,
// warp tile 64x32, 2 CTAs/SM) + cp.async issue split across the ks loop.

// ---------------- problem constants ----------------
#define N_TOK   16384
#define F_DIM   1024
#define B_DIM   512
#define TILE_M  128
#define TILE_F  32
#define GCOLS   128          // 4 gates * TILE_F
#define KC      64           // K elements per chunk (128B fp16 rows)
#define NCHUNK  24           // 1536 / 64
#define THREADS 256
#define STAGES  3

// ---------------- smem layout ----------------
#define ABYTES      (TILE_M * KC * 2)          // 16384
#define BBYTES      (GCOLS * KC * 2)           // 16384
#define STAGE_BYTES (ABYTES + BBYTES)          // 32768
#define GSM_PITCH   36
#define GSM_BYTES   (4 * 128 * GSM_PITCH * 4)  // 73728 (epilogue, unions stages)
#define SM_BIAS     (STAGES * STAGE_BYTES)     // 98304
#define SMEM_TOTAL  (SM_BIAS + 128 * 4)        // 98816  (x2 CTAs = 197632)

static_assert(GSM_BYTES <= STAGES * STAGE_BYTES, "epilogue union");
static_assert(2 * SMEM_TOTAL <= 227 * 1024, "2 CTAs/SM smem");

// ---------------- fp16 scratch ----------------
#define NH  (N_TOK * F_DIM)
#define NX  (N_TOK * B_DIM)
#define NWH (4 * F_DIM * F_DIM)
#define NWX (4 * F_DIM * B_DIM)
__device__ __half g_h [NH];
__device__ __half g_x [NX];
__device__ __half g_wh[NWH];
__device__ __half g_wx[NWX];

// ---------------- helpers ----------------
static __device__ __forceinline__ uint32_t smem_u32(const void* p) {
    uint32_t a;
    asm("{ .reg .u64 t; cvta.to.shared.u64 t, %1; cvt.u32.u64 %0, t; }" : "=r"(a) : "l"(p));
    return a;
}

static __device__ __forceinline__ void cp16(uint32_t dst, const void* src) {
    asm volatile("cp.async.cg.shared.global [%0], [%1], 16;" :: "r"(dst), "l"(src) : "memory");
}

static __device__ __forceinline__ void ldsm4(uint32_t* r, uint32_t addr) {
    asm volatile("ldmatrix.sync.aligned.m8n8.x4.shared.b16 {%0,%1,%2,%3}, [%4];"
                 : "=r"(r[0]), "=r"(r[1]), "=r"(r[2]), "=r"(r[3]) : "r"(addr));
}

static __device__ __forceinline__ void mma_f16(float* c, const uint32_t* a, const uint32_t* b) {
    asm volatile(
        "mma.sync.aligned.m16n8k16.row.col.f32.f16.f16.f32 "
        "{%0,%1,%2,%3}, {%4,%5,%6,%7}, {%8,%9}, {%0,%1,%2,%3};"
        : "+f"(c[0]), "+f"(c[1]), "+f"(c[2]), "+f"(c[3])
        : "r"(a[0]), "r"(a[1]), "r"(a[2]), "r"(a[3]), "r"(b[0]), "r"(b[1]));
}

static __device__ __forceinline__ float sigf(float x) { return 1.0f / (1.0f + __expf(-x)); }
static __device__ __forceinline__ float tanh_fast(float x) {
    return 2.0f / (1.0f + __expf(-2.0f * x)) - 1.0f;
}

// ---------------- merged pre-pass: all four tensors in ONE launch ----------------
__global__ void __launch_bounds__(256) preconv_all(const float4* __restrict__ s_h,
                                                   const float4* __restrict__ s_x,
                                                   const float4* __restrict__ s_wh,
                                                   const float4* __restrict__ s_wx) {
    const int T1 = NH / 8, T2 = T1 + NX / 8, T3 = T2 + NWH / 8, T4 = T3 + NWX / 8;
    int i = blockIdx.x * 256 + threadIdx.x;
    if (i >= T4) return;
    const float4* src;
    uint4* dst;
    int j = i;
    if (i < T1)      { src = s_h;  dst = (uint4*)g_h; }
    else if (i < T2) { src = s_x;  dst = (uint4*)g_x;  j = i - T1; }
    else if (i < T3) { src = s_wh; dst = (uint4*)g_wh; j = i - T2; }
    else             { src = s_wx; dst = (uint4*)g_wx; j = i - T3; }
    float4 a = src[2 * j], b = src[2 * j + 1];
    __half2 p0 = __floats2half2_rn(a.x, a.y);
    __half2 p1 = __floats2half2_rn(a.z, a.w);
    __half2 p2 = __floats2half2_rn(b.x, b.y);
    __half2 p3 = __floats2half2_rn(b.z, b.w);
    uint4 o;
    o.x = *reinterpret_cast<uint32_t*>(&p0);
    o.y = *reinterpret_cast<uint32_t*>(&p1);
    o.z = *reinterpret_cast<uint32_t*>(&p2);
    o.w = *reinterpret_cast<uint32_t*>(&p3);
    dst[j] = o;
}

// ---------------- chunk source resolution ----------------
static __device__ __forceinline__ void chunk_src(int chunk, const __half*& asrc,
                                                 const __half*& wk, int& ld,
                                                 int m_base) {
    if (chunk < 16) {                 // K in [0,1024): h_prev @ Wh^T
        asrc = g_h + (size_t)m_base * F_DIM + chunk * KC;
        wk   = g_wh + chunk * KC;
        ld   = F_DIM;
    } else {                          // K in [1024,1536): behavior @ Wx^T
        asrc = g_x + (size_t)m_base * B_DIM + (chunk - 16) * KC;
        wk   = g_wx + (chunk - 16) * KC;
        ld   = B_DIM;
    }
}

// A-half of a chunk load (4 cp16/thread)
static __device__ __forceinline__ void issue_A(int chunk, int slot, uint32_t sb, int tid,
                                               int m_base) {
    const __half *asrc, *wk; int ld;
    chunk_src(chunk, asrc, wk, ld, m_base);
    const uint32_t abase = sb + (uint32_t)slot * STAGE_BYTES;
#pragma unroll
    for (int i = 0; i < 4; ++i) {     // A: 128 rows x 128B, SW128
        int idx = tid + i * THREADS;
        int row = idx >> 3, u = idx & 7;
        cp16(abase + row * 128 + (uint32_t)((u ^ (row & 7)) << 4),
             asrc + (size_t)row * ld + u * 8);
    }
}

// B-half of a chunk load (4 cp16/thread) + commit
static __device__ __forceinline__ void issue_B(int chunk, int slot, uint32_t sb, int tid,
                                               int m_base, int c_base) {
    const __half *asrc, *wk; int ld;
    chunk_src(chunk, asrc, wk, ld, m_base);
    const uint32_t bbase = sb + (uint32_t)slot * STAGE_BYTES + ABYTES;
#pragma unroll
    for (int i = 0; i < 4; ++i) {     // B: 128 rows x 128B, SW128
        int idx = tid + i * THREADS;
        int rr = idx >> 3, u = idx & 7;
        int g = rr >> 5, r = rr & 31;
        cp16(bbase + rr * 128 + (uint32_t)((u ^ (rr & 7)) << 4),
             wk + (size_t)(g * F_DIM + c_base + r) * ld + u * 8);
    }
    asm volatile("cp.async.commit_group;" ::: "memory");
}

__global__ void __launch_bounds__(THREADS, 2)
lstm_mma_kernel(float* __restrict__ out,
                const float* __restrict__ c_prev,
                const float* __restrict__ bias) {
    extern __shared__ char smem[];
    const uint32_t sb = smem_u32(smem);
    const int tid = threadIdx.x;
    const int lane = tid & 31;
    const int wid = tid >> 5;
    const int warp_m = wid & 1;        // token half (64 rows)
    const int warp_n = wid >> 1;       // gate (0..3), 32 gemm-cols each
    const int la = lane >> 2;          // 0..7
    const int lk = lane & 3;           // 0..3

    const int f_tile = blockIdx.x & 31;
    const int m_tile = blockIdx.x >> 5;
    const int m_base = m_tile * TILE_M;
    const int c_base = f_tile * TILE_F;

    float* bias_s = reinterpret_cast<float*>(smem + SM_BIAS);
    if (tid < 128) bias_s[tid] = bias[(tid >> 5) * F_DIM + c_base + (tid & 31)];

    // ---- per-lane ldmatrix address components ----
    const int q    = lane >> 3;        // quad / matrix index
    const int lrow = lane & 7;
    const uint32_t aStat = (uint32_t)(warp_m * 64 + (q & 1) * 8 + lrow) * 128u;
    const int kqA = q >> 1;
    const uint32_t bStat = (uint32_t)(warp_n * 32 + (q >> 1) * 8 + lrow) * 128u;
    const int kqB = q & 1;

    float acc[4][4][4];
#pragma unroll
    for (int mt = 0; mt < 4; ++mt)
#pragma unroll
        for (int nt = 0; nt < 4; ++nt)
#pragma unroll
            for (int j = 0; j < 4; ++j) acc[mt][nt][j] = 0.0f;

    issue_A(0, 0, sb, tid, m_base); issue_B(0, 0, sb, tid, m_base, c_base);
    issue_A(1, 1, sb, tid, m_base); issue_B(1, 1, sb, tid, m_base, c_base);

#pragma unroll 3
    for (int ch = 0; ch < NCHUNK; ++ch) {
        if (ch < NCHUNK - 1) {
            asm volatile("cp.async.wait_group 1;" ::: "memory");
        } else {
            asm volatile("cp.async.wait_group 0;" ::: "memory");
        }
        __syncthreads();

        const uint32_t abase = sb + (uint32_t)(ch % STAGES) * STAGE_BYTES;
        const uint32_t bbase = abase + ABYTES;
        const bool more = (ch + 2 < NCHUNK);
        const int nslot = (ch + 2) % STAGES;

#pragma unroll
        for (int ks = 0; ks < 4; ++ks) {          // 4 x K=16 per chunk
            const uint32_t uA = (uint32_t)(((2 * ks + kqA) ^ lrow) << 4);
            const uint32_t uB = (uint32_t)(((2 * ks + kqB) ^ lrow) << 4);

            uint32_t af[4][4];
            uint32_t bq[2][4];                    // each x4 covers 2 n-tiles
            // first-use fragments first so MMAs can start while the rest load
            ldsm4(af[0], abase + aStat + uA);
            ldsm4(bq[0], bbase + bStat + uB);
            ldsm4(af[1], abase + aStat + 2048u + uA);
            ldsm4(bq[1], bbase + bStat + 2048u + uB);
            ldsm4(af[2], abase + aStat + 4096u + uA);
            ldsm4(af[3], abase + aStat + 6144u + uA);

#pragma unroll
            for (int mt = 0; mt < 4; ++mt)
#pragma unroll
                for (int nt = 0; nt < 4; ++nt)
                    mma_f16(acc[mt][nt], af[mt], &bq[nt >> 1][(nt & 1) * 2]);

            // spread next-chunk cp.async across the ks loop (LSU smoothing)
            if (ks == 1 && more) issue_A(ch + 2, nslot, sb, tid, m_base);
            if (ks == 3 && more) issue_B(ch + 2, nslot, sb, tid, m_base, c_base);
        }
    }

    // ---- prefetch c_prev into registers (latency hides under gsm writes) ----
    const float* cpg = c_prev + (size_t)m_base * F_DIM + c_base;
    float cpv[(TILE_M * TILE_F) / THREADS];
#pragma unroll
    for (int i = 0; i < (TILE_M * TILE_F) / THREADS; ++i) {
        const int idx = tid + i * THREADS;
        cpv[i] = cpg[(size_t)(idx >> 5) * F_DIM + (idx & 31)];
    }

    __syncthreads();   // stage buffers -> epilogue union

    // ---- epilogue: dump 4 gate tiles (128 x 32 each) to smem ----
    float* gsm = reinterpret_cast<float*>(smem);
#pragma unroll
    for (int mt = 0; mt < 4; ++mt) {
#pragma unroll
        for (int nt = 0; nt < 4; ++nt) {
            const int r0 = warp_m * 64 + mt * 16 + la;
            const int f0 = nt * 8 + 2 * lk;
            const size_t o = ((size_t)(warp_n * 128 + r0)) * GSM_PITCH + f0;
            gsm[o]     = acc[mt][nt][0];
            gsm[o + 1] = acc[mt][nt][1];
            gsm[o + 8 * GSM_PITCH]     = acc[mt][nt][2];
            gsm[o + 8 * GSM_PITCH + 1] = acc[mt][nt][3];
        }
    }
    __syncthreads();

    // ---- gate math + coalesced global I/O ----
    float* og = out + (size_t)m_base * F_DIM + c_base;
#pragma unroll
    for (int i = 0; i < (TILE_M * TILE_F) / THREADS; ++i) {
        const int idx = tid + i * THREADS;
        const int row = idx >> 5;
        const int f = idx & 31;
        const float xi = gsm[((size_t)(0 * 128 + row)) * GSM_PITCH + f] + bias_s[f];
        const float xf = gsm[((size_t)(1 * 128 + row)) * GSM_PITCH + f] + bias_s[32 + f];
        const float xg = gsm[((size_t)(2 * 128 + row)) * GSM_PITCH + f] + bias_s[64 + f];
        const float xo = gsm[((size_t)(3 * 128 + row)) * GSM_PITCH + f] + bias_s[96 + f];
        const float cv = sigf(xf) * cpv[i] + sigf(xi) * tanh_fast(xg);
        og[(size_t)row * F_DIM + f] = sigf(xo) * tanh_fast(cv);
    }
}

extern "C" void kernel_launch(void* const* d_in, const int* in_sizes, int n_in,
                              void* d_out, int out_size) {
    const float* behavior = (const float*)d_in[0];
    const float* h_prev   = (const float*)d_in[1];
    const float* c_prev   = (const float*)d_in[2];
    const float* Wh       = (const float*)d_in[3];
    const float* Wx       = (const float*)d_in[4];
    const float* bias     = (const float*)d_in[5];

    const int total8 = NH / 8 + NX / 8 + NWH / 8 + NWX / 8;
    preconv_all<<<(total8 + 255) / 256, 256>>>(
        (const float4*)h_prev, (const float4*)behavior,
        (const float4*)Wh, (const float4*)Wx);

    cudaFuncSetAttribute(lstm_mma_kernel,
                         cudaFuncAttributeMaxDynamicSharedMemorySize, SMEM_TOTAL);

    const int grid = (N_TOK / TILE_M) * (F_DIM / TILE_F);  // 128 * 32 = 4096
    lstm_mma_kernel<<<grid, THREADS, SMEM_TOTAL>>>((float*)d_out, c_prev, bias);
}

// round 13
// speedup vs baseline: 1.3922x; 1.0439x over previous
#include <cuda_runtime.h>
#include <cuda_fp16.h>
#include <cstdint>
#include <cstddef>

// Harness PTX target is base sm_103 — no tcgen05. Tensor path: mma.sync f16 m16n8k16
// (fallback HMMA, rt~8 cyc/SMSP -> ~341us busy floor). R11 shape + mbarrier
// producer/consumer pipeline. R12 deadlock fix: cp.async.mbarrier.arrive needs
// .noinc (non-noinc form increments pending count -> barrier never flips).

// ---------------- problem constants ----------------
#define N_TOK   16384
#define F_DIM   1024
#define B_DIM   512
#define TILE_M  128
#define TILE_F  32
#define GCOLS   128          // 4 gates * TILE_F
#define KC      64           // K elements per chunk (128B fp16 rows)
#define NCHUNK  24           // 1536 / 64
#define THREADS 256
#define STAGES  3

// ---------------- smem layout ----------------
#define ABYTES      (TILE_M * KC * 2)          // 16384
#define BBYTES      (GCOLS * KC * 2)           // 16384
#define STAGE_BYTES (ABYTES + BBYTES)          // 32768
#define GSM_PITCH   36
#define GSM_BYTES   (4 * 128 * GSM_PITCH * 4)  // 73728 (epilogue, unions stages)
#define SM_BIAS     (STAGES * STAGE_BYTES)     // 98304
#define SM_MBAR     (SM_BIAS + 512)            // 6 mbarriers x 8B
#define SMEM_TOTAL  (SM_MBAR + 64)             // 98880  (x2 CTAs = 197760)

static_assert(GSM_BYTES <= STAGES * STAGE_BYTES, "epilogue union");
static_assert(2 * SMEM_TOTAL <= 227 * 1024, "2 CTAs/SM smem");

// ---------------- fp16 scratch ----------------
#define NH  (N_TOK * F_DIM)
#define NX  (N_TOK * B_DIM)
#define NWH (4 * F_DIM * F_DIM)
#define NWX (4 * F_DIM * B_DIM)
__device__ __half g_h [NH];
__device__ __half g_x [NX];
__device__ __half g_wh[NWH];
__device__ __half g_wx[NWX];

// ---------------- helpers ----------------
static __device__ __forceinline__ uint32_t smem_u32(const void* p) {
    uint32_t a;
    asm("{ .reg .u64 t; cvta.to.shared.u64 t, %1; cvt.u32.u64 %0, t; }" : "=r"(a) : "l"(p));
    return a;
}

static __device__ __forceinline__ void cp16(uint32_t dst, const void* src) {
    asm volatile("cp.async.cg.shared.global [%0], [%1], 16;" :: "r"(dst), "l"(src) : "memory");
}

static __device__ __forceinline__ void mbar_init(uint32_t a, uint32_t cnt) {
    asm volatile("mbarrier.init.shared.b64 [%0], %1;" :: "r"(a), "r"(cnt) : "memory");
}
static __device__ __forceinline__ void mbar_arrive(uint32_t a) {
    asm volatile("mbarrier.arrive.shared.b64 _, [%0];" :: "r"(a) : "memory");
}
static __device__ __forceinline__ void cp_arrive(uint32_t a) {
    // .noinc is load-bearing: the plain form increments the pending count by 1
    // before arriving (net zero) and the barrier would never complete its phase.
    asm volatile("cp.async.mbarrier.arrive.noinc.shared.b64 [%0];" :: "r"(a) : "memory");
}
static __device__ __forceinline__ void mbar_wait(uint32_t a, uint32_t parity) {
    asm volatile(
        "{\n\t.reg .pred P;\n\t"
        "WL_%=:\n\t"
        "mbarrier.try_wait.parity.shared.b64 P, [%0], %1;\n\t"
        "@!P bra WL_%=;\n\t}"
        :: "r"(a), "r"(parity) : "memory");
}

static __device__ __forceinline__ void ldsm4(uint32_t* r, uint32_t addr) {
    asm volatile("ldmatrix.sync.aligned.m8n8.x4.shared.b16 {%0,%1,%2,%3}, [%4];"
                 : "=r"(r[0]), "=r"(r[1]), "=r"(r[2]), "=r"(r[3]) : "r"(addr));
}

static __device__ __forceinline__ void mma_f16(float* c, const uint32_t* a, const uint32_t* b) {
    asm volatile(
        "mma.sync.aligned.m16n8k16.row.col.f32.f16.f16.f32 "
        "{%0,%1,%2,%3}, {%4,%5,%6,%7}, {%8,%9}, {%0,%1,%2,%3};"
        : "+f"(c[0]), "+f"(c[1]), "+f"(c[2]), "+f"(c[3])
        : "r"(a[0]), "r"(a[1]), "r"(a[2]), "r"(a[3]), "r"(b[0]), "r"(b[1]));
}

static __device__ __forceinline__ float sigf(float x) { return 1.0f / (1.0f + __expf(-x)); }
static __device__ __forceinline__ float tanh_fast(float x) {
    return 2.0f / (1.0f + __expf(-2.0f * x)) - 1.0f;
}

// ---------------- merged pre-pass: all four tensors in ONE launch ----------------
__global__ void __launch_bounds__(256) preconv_all(const float4* __restrict__ s_h,
                                                   const float4* __restrict__ s_x,
                                                   const float4* __restrict__ s_wh,
                                                   const float4* __restrict__ s_wx) {
    const int T1 = NH / 8, T2 = T1 + NX / 8, T3 = T2 + NWH / 8, T4 = T3 + NWX / 8;
    int i = blockIdx.x * 256 + threadIdx.x;
    if (i >= T4) return;
    const float4* src;
    uint4* dst;
    int j = i;
    if (i < T1)      { src = s_h;  dst = (uint4*)g_h; }
    else if (i < T2) { src = s_x;  dst = (uint4*)g_x;  j = i - T1; }
    else if (i < T3) { src = s_wh; dst = (uint4*)g_wh; j = i - T2; }
    else             { src = s_wx; dst = (uint4*)g_wx; j = i - T3; }
    float4 a = src[2 * j], b = src[2 * j + 1];
    __half2 p0 = __floats2half2_rn(a.x, a.y);
    __half2 p1 = __floats2half2_rn(a.z, a.w);
    __half2 p2 = __floats2half2_rn(b.x, b.y);
    __half2 p3 = __floats2half2_rn(b.z, b.w);
    uint4 o;
    o.x = *reinterpret_cast<uint32_t*>(&p0);
    o.y = *reinterpret_cast<uint32_t*>(&p1);
    o.z = *reinterpret_cast<uint32_t*>(&p2);
    o.w = *reinterpret_cast<uint32_t*>(&p3);
    dst[j] = o;
}

// ---------------- chunk source resolution ----------------
static __device__ __forceinline__ void chunk_src(int chunk, const __half*& asrc,
                                                 const __half*& wk, int& ld,
                                                 int m_base) {
    if (chunk < 16) {                 // K in [0,1024): h_prev @ Wh^T
        asrc = g_h + (size_t)m_base * F_DIM + chunk * KC;
        wk   = g_wh + chunk * KC;
        ld   = F_DIM;
    } else {                          // K in [1024,1536): behavior @ Wx^T
        asrc = g_x + (size_t)m_base * B_DIM + (chunk - 16) * KC;
        wk   = g_wx + (chunk - 16) * KC;
        ld   = B_DIM;
    }
}

// A-half of a chunk load (4 cp16/thread)
static __device__ __forceinline__ void issue_A(int chunk, int slot, uint32_t sb, int tid,
                                               int m_base) {
    const __half *asrc, *wk; int ld;
    chunk_src(chunk, asrc, wk, ld, m_base);
    const uint32_t abase = sb + (uint32_t)slot * STAGE_BYTES;
#pragma unroll
    for (int i = 0; i < 4; ++i) {     // A: 128 rows x 128B, SW128
        int idx = tid + i * THREADS;
        int row = idx >> 3, u = idx & 7;
        cp16(abase + row * 128 + (uint32_t)((u ^ (row & 7)) << 4),
             asrc + (size_t)row * ld + u * 8);
    }
}

// B-half of a chunk load (4 cp16/thread)
static __device__ __forceinline__ void issue_B(int chunk, int slot, uint32_t sb, int tid,
                                               int m_base, int c_base) {
    const __half *asrc, *wk; int ld;
    chunk_src(chunk, asrc, wk, ld, m_base);
    const uint32_t bbase = sb + (uint32_t)slot * STAGE_BYTES + ABYTES;
#pragma unroll
    for (int i = 0; i < 4; ++i) {     // B: 128 rows x 128B, SW128
        int idx = tid + i * THREADS;
        int rr = idx >> 3, u = idx & 7;
        int g = rr >> 5, r = rr & 31;
        cp16(bbase + rr * 128 + (uint32_t)((u ^ (rr & 7)) << 4),
             wk + (size_t)(g * F_DIM + c_base + r) * ld + u * 8);
    }
}

__global__ void __launch_bounds__(THREADS, 2)
lstm_mma_kernel(float* __restrict__ out,
                const float* __restrict__ c_prev,
                const float* __restrict__ bias) {
    extern __shared__ char smem[];
    const uint32_t sb = smem_u32(smem);
    const int tid = threadIdx.x;
    const int lane = tid & 31;
    const int wid = tid >> 5;
    const int warp_m = wid & 1;        // token half (64 rows)
    const int warp_n = wid >> 1;       // gate (0..3), 32 gemm-cols each
    const int la = lane >> 2;          // 0..7
    const int lk = lane & 3;           // 0..3

    const int f_tile = blockIdx.x & 31;
    const int m_tile = blockIdx.x >> 5;
    const int m_base = m_tile * TILE_M;
    const int c_base = f_tile * TILE_F;

    // mbarriers: full[s] at SM_MBAR + 8s (count 256), empty[s] at +24+8s (count 8 warps)
    const uint32_t mb = sb + SM_MBAR;
    if (tid == 0) {
#pragma unroll
        for (int s = 0; s < 3; ++s) {
            mbar_init(mb + 8u * s, 256);
            mbar_init(mb + 24u + 8u * s, 8);
        }
    }
    float* bias_s = reinterpret_cast<float*>(smem + SM_BIAS);
    if (tid < 128) bias_s[tid] = bias[(tid >> 5) * F_DIM + c_base + (tid & 31)];
    __syncthreads();                   // mbarriers initialized

    // ---- per-lane ldmatrix address components ----
    const int q    = lane >> 3;        // quad / matrix index
    const int lrow = lane & 7;
    const uint32_t aStat = (uint32_t)(warp_m * 64 + (q & 1) * 8 + lrow) * 128u;
    const int kqA = q >> 1;
    const uint32_t bStat = (uint32_t)(warp_n * 32 + (q >> 1) * 8 + lrow) * 128u;
    const int kqB = q & 1;

    float acc[4][4][4];
#pragma unroll
    for (int mt = 0; mt < 4; ++mt)
#pragma unroll
        for (int nt = 0; nt < 4; ++nt)
#pragma unroll
            for (int j = 0; j < 4; ++j) acc[mt][nt][j] = 0.0f;

    // prologue: stages 0,1 (no empty-wait needed on first use)
    issue_A(0, 0, sb, tid, m_base); issue_B(0, 0, sb, tid, m_base, c_base);
    cp_arrive(mb + 0u);
    issue_A(1, 1, sb, tid, m_base); issue_B(1, 1, sb, tid, m_base, c_base);
    cp_arrive(mb + 8u);

    for (int blk = 0; blk < 8; ++blk) {
#pragma unroll
        for (int s = 0; s < 3; ++s) {
            const int ch = blk * 3 + s;
            const uint32_t pf = (uint32_t)(blk & 1);
            mbar_wait(mb + 8u * s, pf);          // chunk ch data ready (acquire)

            const uint32_t abase = sb + (uint32_t)s * STAGE_BYTES;
            const uint32_t bbase = abase + ABYTES;
            const int c = ch + 2;                // chunk to prefetch
            const int cs = (s + 2) % 3;          // its stage
            const bool more = (c < NCHUNK);
            // empty parity for chunk c's stage: (c/3 - 1) & 1
            const uint32_t pe = (s == 0) ? (uint32_t)((blk - 1) & 1)
                                         : (uint32_t)(blk & 1);

#pragma unroll
            for (int ks = 0; ks < 4; ++ks) {     // 4 x K=16 per chunk
                const uint32_t uA = (uint32_t)(((2 * ks + kqA) ^ lrow) << 4);
                const uint32_t uB = (uint32_t)(((2 * ks + kqB) ^ lrow) << 4);

                uint32_t af[4][4];
                uint32_t bq[2][4];               // each x4 covers 2 n-tiles
                ldsm4(af[0], abase + aStat + uA);
                ldsm4(bq[0], bbase + bStat + uB);
                ldsm4(af[1], abase + aStat + 2048u + uA);
                ldsm4(bq[1], bbase + bStat + 2048u + uB);
                ldsm4(af[2], abase + aStat + 4096u + uA);
                ldsm4(af[3], abase + aStat + 6144u + uA);

#pragma unroll
                for (int mt = 0; mt < 4; ++mt)
#pragma unroll
                    for (int nt = 0; nt < 4; ++nt)
                        mma_f16(acc[mt][nt], af[mt], &bq[nt >> 1][(nt & 1) * 2]);

                // spread next-chunk cp.async across the ks loop
                if (ks == 1 && more) {
                    if (c >= 3) mbar_wait(mb + 24u + 8u * cs, pe);  // stage free
                    issue_A(c, cs, sb, tid, m_base);
                }
                if (ks == 3 && more) {
                    issue_B(c, cs, sb, tid, m_base, c_base);
                    cp_arrive(mb + 8u * cs);     // full[cs] when copies land
                }
            }

            if (lane == 0) mbar_arrive(mb + 24u + 8u * s);   // warp done with stage s
        }
    }

    // ---- prefetch c_prev into registers (latency hides under gsm writes) ----
    const float* cpg = c_prev + (size_t)m_base * F_DIM + c_base;
    float cpv[(TILE_M * TILE_F) / THREADS];
#pragma unroll
    for (int i = 0; i < (TILE_M * TILE_F) / THREADS; ++i) {
        const int idx = tid + i * THREADS;
        cpv[i] = cpg[(size_t)(idx >> 5) * F_DIM + (idx & 31)];
    }

    __syncthreads();   // all warps done with stage buffers -> epilogue union

    // ---- epilogue: dump 4 gate tiles (128 x 32 each) to smem ----
    float* gsm = reinterpret_cast<float*>(smem);
#pragma unroll
    for (int mt = 0; mt < 4; ++mt) {
#pragma unroll
        for (int nt = 0; nt < 4; ++nt) {
            const int r0 = warp_m * 64 + mt * 16 + la;
            const int f0 = nt * 8 + 2 * lk;
            const size_t o = ((size_t)(warp_n * 128 + r0)) * GSM_PITCH + f0;
            gsm[o]     = acc[mt][nt][0];
            gsm[o + 1] = acc[mt][nt][1];
            gsm[o + 8 * GSM_PITCH]     = acc[mt][nt][2];
            gsm[o + 8 * GSM_PITCH + 1] = acc[mt][nt][3];
        }
    }
    __syncthreads();

    // ---- gate math + coalesced global I/O ----
    float* og = out + (size_t)m_base * F_DIM + c_base;
#pragma unroll
    for (int i = 0; i < (TILE_M * TILE_F) / THREADS; ++i) {
        const int idx = tid + i * THREADS;
        const int row = idx >> 5;
        const int f = idx & 31;
        const float xi = gsm[((size_t)(0 * 128 + row)) * GSM_PITCH + f] + bias_s[f];
        const float xf = gsm[((size_t)(1 * 128 + row)) * GSM_PITCH + f] + bias_s[32 + f];
        const float xg = gsm[((size_t)(2 * 128 + row)) * GSM_PITCH + f] + bias_s[64 + f];
        const float xo = gsm[((size_t)(3 * 128 + row)) * GSM_PITCH + f] + bias_s[96 + f];
        const float cv = sigf(xf) * cpv[i] + sigf(xi) * tanh_fast(xg);
        og[(size_t)row * F_DIM + f] = sigf(xo) * tanh_fast(cv);
    }
}

extern "C" void kernel_launch(void* const* d_in, const int* in_sizes, int n_in,
                              void* d_out, int out_size) {
    const float* behavior = (const float*)d_in[0];
    const float* h_prev   = (const float*)d_in[1];
    const float* c_prev   = (const float*)d_in[2];
    const float* Wh       = (const float*)d_in[3];
    const float* Wx       = (const float*)d_in[4];
    const float* bias     = (const float*)d_in[5];

    const int total8 = NH / 8 + NX / 8 + NWH / 8 + NWX / 8;
    preconv_all<<<(total8 + 255) / 256, 256>>>(
        (const float4*)h_prev, (const float4*)behavior,
        (const float4*)Wh, (const float4*)Wx);

    cudaFuncSetAttribute(lstm_mma_kernel,
                         cudaFuncAttributeMaxDynamicSharedMemorySize, SMEM_TOTAL);

    const int grid = (N_TOK / TILE_M) * (F_DIM / TILE_F);  // 128 * 32 = 4096
    lstm_mma_kernel<<<grid, THREADS, SMEM_TOTAL>>>((float*)d_out, c_prev, bias);
}